// round 17
// baseline (speedup 1.0000x reference)
#include <cuda_runtime.h>
#include <cstdint>

#define AN 13824          // 24*24*24 anchors
#define NT 288            // threads per block: 3456/288 = 12 float4 each, no tail
#define NV 3456           // AN/4
#define NL 12             // float4 loads per thread
#define TK 60             // TOPK
#define NMSK 20           // NMS_TOPK
#define SEGSZ 48          // per-warp capacity: mean 18.8, sigma 4.3 -> ~6.8 sigma
#define NWARP 9
#define CAP (SEGSZ * NWARP)   // 432
#define NB 256            // batches
#define THRF 2.25f        // fast-path threshold: ~169+-13 qualifiers per batch

__device__ __forceinline__ unsigned int fkey(float x) {
    unsigned int b = __float_as_uint(x);
    return (b & 0x80000000u) ? ~b : (b | 0x80000000u);
}
__device__ __forceinline__ float fkey_inv(unsigned int u) {
    unsigned int b = (u & 0x80000000u) ? (u & 0x7fffffffu) : ~u;
    return __uint_as_float(b);
}
// qualifiers are positive floats -> fkey reduces to one OR
__device__ __forceinline__ unsigned long long mkkey(float x, int idx) {
    return ((unsigned long long)(__float_as_uint(x) | 0x80000000u) << 14) |
           (unsigned long long)(16383 - idx);
}

__global__ __launch_bounds__(NT, 2)
void detect_fused_kernel(const float* __restrict__ cls,
                         const float* __restrict__ shp,
                         const float* __restrict__ off,
                         float* __restrict__ out)
{
    const int b    = blockIdx.x;
    const int t    = threadIdx.x;
    const int lane = t & 31;
    const int wid  = t >> 5;

    __shared__ unsigned long long s_seg[NWARP][SEGSZ];
    __shared__ unsigned long long s_cand[CAP];
    __shared__ int   s_wc[NWARP];
    __shared__ int   s_segoff[NWARP];
    __shared__ int   s_tot, s_maxseg;
    __shared__ int   s_wcnt[2][NWARP];
    __shared__ int   s_ncand;
    __shared__ unsigned long long s_key[TK];
    __shared__ float s_sc[TK];
    __shared__ unsigned int s_valid[2];
    __shared__ int   s_crow[NMSK];
    __shared__ int   s_nc;
    __shared__ float s_gv[6][NMSK];
    __shared__ float s_ctr[NMSK][3], s_sz[NMSK][3];
    __shared__ float s_lo[NMSK][3], s_hi[NMSK][3], s_vol[NMSK];
    __shared__ unsigned int s_m[NMSK];
    __shared__ unsigned int s_kept;

    if (lane == 0) s_wc[wid] = 0;
    __syncwarp();

    // ---------------- Phase 1a: 12 clean float4 loads ----------------
    const float4* cb4 = (const float4*)(cls + (size_t)b * AN);
    float4 v[NL];
#pragma unroll
    for (int j = 0; j < NL; j++)
        v[j] = __ldg(&cb4[t + NT * j]);

    // ---------------- Phase 1b: max-compressed test (1 compare per 4 elements) ----------------
    // fmaxf of 4 >= THRF  <=>  any of the 4 >= THRF (NaNs dropped by FMNMX, never qualify).
#pragma unroll
    for (int j = 0; j < NL; j++) {
        float mx = fmaxf(fmaxf(v[j].x, v[j].y), fmaxf(v[j].z, v[j].w));
        if (mx >= THRF) {                      // rare: ~4.7% of thread-groups
            int base = 4 * (t + NT * j);
            if (v[j].x >= THRF) { int p = atomicAdd(&s_wc[wid], 1); if (p < SEGSZ) s_seg[wid][p] = mkkey(v[j].x, base + 0); }
            if (v[j].y >= THRF) { int p = atomicAdd(&s_wc[wid], 1); if (p < SEGSZ) s_seg[wid][p] = mkkey(v[j].y, base + 1); }
            if (v[j].z >= THRF) { int p = atomicAdd(&s_wc[wid], 1); if (p < SEGSZ) s_seg[wid][p] = mkkey(v[j].z, base + 2); }
            if (v[j].w >= THRF) { int p = atomicAdd(&s_wc[wid], 1); if (p < SEGSZ) s_seg[wid][p] = mkkey(v[j].w, base + 3); }
        }
    }
    __syncthreads();

    // warp 0: prefix over 9 segment counts
    if (wid == 0) {
        int cnt = (lane < NWARP) ? s_wc[lane] : 0;
        int incl = cnt;
#pragma unroll
        for (int o = 1; o < 16; o <<= 1) {
            int vv = __shfl_up_sync(0xffffffffu, incl, o);
            if (lane >= o) incl += vv;
        }
        if (lane < NWARP) s_segoff[lane] = incl - cnt;
        int mx = __reduce_max_sync(0xffffffffu, (lane < NWARP) ? cnt : 0);
        int tt = __shfl_sync(0xffffffffu, incl, NWARP - 1);
        if (lane == 0) { s_tot = tt; s_maxseg = mx; }
    }
    __syncthreads();

    const int tot = s_tot;

    if (tot >= TK && tot <= CAP && s_maxseg <= SEGSZ) {
        // ================= FAST PATH (always taken for N(0,1) data) =================
        {
            int n = s_wc[wid];
            if (n > SEGSZ) n = SEGSZ;
            int base = s_segoff[wid];
            for (int p = lane; p < n; p += 32)
                s_cand[base + p] = s_seg[wid][p];
        }
        __syncthreads();
        // exact ranking -> top-20 keys (all top-60 valid: sigmoid(>=2.25) > 0.15)
        for (int cc2 = t; cc2 < tot; cc2 += NT) {
            unsigned long long k = s_cand[cc2];
            int r = 0;
#pragma unroll 4
            for (int m = 0; m < tot; m++)
                r += (s_cand[m] > k);
            if (r < NMSK) s_key[r] = k;
        }
        if (t == 0) s_nc = NMSK;
        if (t < NMSK) s_crow[t] = t;
        __syncthreads();
        if (t < NMSK) {
            float logit = fkey_inv((unsigned int)(s_key[t] >> 14));
            s_sc[t] = 1.0f / (1.0f + expf(-logit));
        }
        __syncthreads();
    } else {
        // ================= FALLBACK (exact, never taken for this data) =================
        const float* cb = cls + (size_t)b * AN;
        unsigned int T = 0;
        for (int bit = 10; bit >= 0; bit--) {
            unsigned int candT = T | (1u << bit);
            unsigned int Tsh = candT << 21;
            int cc = 0;
            for (int i = t; i < AN; i += NT)
                cc += (fkey(__ldg(&cb[i])) >= Tsh);
            unsigned int ws = __reduce_add_sync(0xffffffffu, (unsigned int)cc);
            int buf = bit & 1;
            if (lane == 0) s_wcnt[buf][wid] = (int)ws;
            __syncthreads();
            int tt = 0;
#pragma unroll
            for (int w = 0; w < NWARP; w++)
                tt += s_wcnt[buf][w];
            if (tt >= TK) T = candT;
            __syncthreads();
        }
        unsigned int cut = T << 21;
        if (cut == 0) cut = 1;
        if (t == 0) s_ncand = 0;
        __syncthreads();
        for (int i = t; i < AN; i += NT) {
            unsigned int k = fkey(__ldg(&cb[i]));
            if (k >= cut) {
                int p = atomicAdd(&s_ncand, 1);
                if (p < CAP)
                    s_cand[p] = ((unsigned long long)k << 14) |
                                (unsigned long long)(16383 - i);
            }
        }
        __syncthreads();
        int C = s_ncand;
        if (C > CAP) C = CAP;
        for (int cc2 = t; cc2 < C; cc2 += NT) {
            unsigned long long k = s_cand[cc2];
            int r = 0;
            for (int m = 0; m < C; m++)
                r += (s_cand[m] > k);
            if (r < TK) s_key[r] = k;
        }
        __syncthreads();
        float sc = 0.0f;
        if (t < TK) {
            float logit = fkey_inv((unsigned int)(s_key[t] >> 14));
            sc = 1.0f / (1.0f + expf(-logit));
            s_sc[t] = sc;
        }
        {
            unsigned int vb = __ballot_sync(0xffffffffu, (t < TK) && (sc > 0.15f));
            if (wid < 2 && lane == 0) s_valid[wid] = vb;
        }
        __syncthreads();
        unsigned long long valid = ((unsigned long long)s_valid[1] << 32) | s_valid[0];
        int nc2 = __popcll(valid);
        if (nc2 > NMSK) nc2 = NMSK;
        if (t == 0) s_nc = nc2;
        if (t < TK) {
            if ((valid >> t) & 1ull) {
                int rv = __popcll(valid & ((1ull << t) - 1ull));
                if (rv < NMSK) s_crow[rv] = t;
            }
        }
        __syncthreads();
    }

    const int nc = s_nc;

    // ---------------- Phase 4: gather off/shp for cand rows (<=120 loads) ----------------
    if (t < 6 * NMSK) {
        int ci = t / 6, comp = t - ci * 6;
        if (ci < nc) {
            int idx = 16383 - (int)(s_key[s_crow[ci]] & 16383ull);
            size_t base = (size_t)b * 3 * AN;
            const float* src = (comp < 3) ? (off + base + (size_t)comp * AN)
                                          : (shp + base + (size_t)(comp - 3) * AN);
            s_gv[comp][ci] = __ldg(&src[idx]);
        }
    }
    __syncthreads();

    // ---------------- Phase 5: box build for cand rows ----------------
    if (t < nc) {
        int idx = 16383 - (int)(s_key[s_crow[t]] & 16383ull);
        int z   = idx / 576;
        int rem = idx - z * 576;
        int y   = rem / 24;
        int x   = rem - y * 24;
        float cz = ((float)z + s_gv[0][t]) * 4.0f;   // stride = 96/24 = 4
        float cy = ((float)y + s_gv[1][t]) * 4.0f;
        float cx = ((float)x + s_gv[2][t]) * 4.0f;
        float dz = 2.0f * s_gv[3][t];
        float dy = 2.0f * s_gv[4][t];
        float dx = 2.0f * s_gv[5][t];
        s_ctr[t][0] = cz; s_ctr[t][1] = cy; s_ctr[t][2] = cx;
        s_sz[t][0] = dz;  s_sz[t][1] = dy;  s_sz[t][2] = dx;
        s_lo[t][0] = cz - dz * 0.5f; s_lo[t][1] = cy - dy * 0.5f; s_lo[t][2] = cx - dx * 0.5f;
        s_hi[t][0] = cz + dz * 0.5f; s_hi[t][1] = cy + dy * 0.5f; s_hi[t][2] = cx + dx * 0.5f;
        s_vol[t] = dz * dy * dx;
    }
    __syncthreads();

    // ---------------- Phase 6: IoU bitmask among cand rows (<=20x20) ----------------
    if (t < nc) {
        float l0 = s_lo[t][0], l1 = s_lo[t][1], l2 = s_lo[t][2];
        float h0 = s_hi[t][0], h1 = s_hi[t][1], h2 = s_hi[t][2];
        float vi = s_vol[t];
        unsigned int m = 0;
        for (int j = 0; j < nc; j++) {
            float iz = fminf(h0, s_hi[j][0]) - fmaxf(l0, s_lo[j][0]);
            float iy = fminf(h1, s_hi[j][1]) - fmaxf(l1, s_lo[j][1]);
            float ix = fminf(h2, s_hi[j][2]) - fmaxf(l2, s_lo[j][2]);
            float inter = fmaxf(iz, 0.0f) * fmaxf(iy, 0.0f) * fmaxf(ix, 0.0f);
            float uni = vi + s_vol[j] - inter;
            float iou = inter / fmaxf(uni, 1e-8f);
            unsigned int hit = (iou > 0.05f) && (j != t);
            m |= hit << j;
        }
        s_m[t] = m;
    }
    __syncthreads();

    // ---------------- Phase 7: serial bitmask NMS ----------------
    if (t == 0) {
        unsigned int supp = 0, kept = 0;
#pragma unroll
        for (int ci = 0; ci < NMSK; ci++) {
            if (ci < nc) {
                unsigned int keep = !((supp >> ci) & 1u);
                kept |= keep << ci;
                if (keep) supp |= s_m[ci];
            }
        }
        s_kept = kept;
    }
    __syncthreads();

    // ---------------- Phase 8: output (kept in rank order, -1 padding) ----------------
    float* ob = out + (size_t)b * TK * 8;
    if (t < TK) {
        unsigned int kept = s_kept;
        int nk = __popc(kept);
        if (t < nk) {
            int ci = 0, c2 = t;
#pragma unroll
            for (int q = 0; q < NMSK; q++) {
                if ((kept >> q) & 1u) {
                    if (c2 == 0) { ci = q; }
                    c2--;
                }
            }
            float4* o4 = (float4*)(ob + t * 8);
            o4[0] = make_float4(1.0f, s_sc[s_crow[ci]], s_ctr[ci][0], s_ctr[ci][1]);
            o4[1] = make_float4(s_ctr[ci][2], s_sz[ci][0], s_sz[ci][1], s_sz[ci][2]);
        } else {
            float4* o4 = (float4*)(ob + t * 8);
            o4[0] = make_float4(-1.0f, -1.0f, -1.0f, -1.0f);
            o4[1] = make_float4(-1.0f, -1.0f, -1.0f, -1.0f);
        }
    }
}

extern "C" void kernel_launch(void* const* d_in, const int* in_sizes, int n_in,
                              void* d_out, int out_size)
{
    const float* cls = (const float*)d_in[0];
    const float* shp = (const float*)d_in[1];
    const float* off = (const float*)d_in[2];
    float* out = (float*)d_out;
    detect_fused_kernel<<<NB, NT>>>(cls, shp, off, out);
}